// round 15
// baseline (speedup 1.0000x reference)
#include <cuda_runtime.h>
#include <cuda_fp16.h>

// Problem constants (fixed by the reference: B=4, C=32, H=64, W=64, NW=64)
#define NW_   64
#define HW_   4096
#define C_    32
#define B_    4
#define TPB   256
#define PPT   2
#define TILES (HW_ / (TPB * PPT))   // 8 tiles per (b,c) image

typedef unsigned long long u64;

// Packed f32x2 FMA (sm_100+; only reachable via PTX). Per-lane rn fp32 FMA:
// bit-identical to two scalar fmaf.
__device__ __forceinline__ u64 fma2(u64 a, u64 b, u64 c) {
    u64 d;
    asm("fma.rn.f32x2 %0, %1, %2, %3;" : "=l"(d) : "l"(a), "l"(b), "l"(c));
    return d;
}
__device__ __forceinline__ u64 pack2(float lo, float hi) {
    u64 d;
    asm("mov.b64 %0, {%1, %2};" : "=l"(d) : "f"(lo), "f"(hi));
    return d;
}

// Unpack a packed f32x2 pair and convert to f16x2 (one CVT), then one packed
// MUFU exp2 for both pixels.
__device__ __forceinline__ __half2 packed_exp2(u64 g) {
    float a0, a1;
    asm("mov.b64 {%0, %1}, %2;" : "=f"(a0), "=f"(a1) : "l"(g));  // reg-alias, free
    unsigned u;
    asm("cvt.rn.f16x2.f32 %0, %1, %2;" : "=r"(u) : "f"(a1), "f"(a0)); // lo=a0
    __half2 h = *reinterpret_cast<__half2*>(&u);
    return h2exp2(h);
}

struct __align__(8) WPair { __half2 wr2, wi2; };   // {wr,wr},{wi,wi} -> 1 LDS.64

__global__ __launch_bounds__(TPB) void cplx_rbf_kernel(
    const float* __restrict__ x_real, const float* __restrict__ x_imag,
    const float* __restrict__ w_real, const float* __restrict__ w_imag,
    const float* __restrict__ b_real, const float* __restrict__ b_imag,
    const float* __restrict__ mu_real, const float* __restrict__ mu_imag,
    const float* __restrict__ stddev,
    float* __restrict__ out)
{
    // Coefficients pre-replicated as {v,v} f32 pairs: zero pack MOVs in the
    // mainloop. 2 x LDS.128 + 1 x LDS.64 per iter, all broadcast.
    __shared__ ulonglong2 s_ab[NW_];   // {A,A}, {B,B}
    __shared__ ulonglong2 s_cd[NW_];   // {C,C}, {D,D}
    __shared__ WPair      s_w[NW_];    // weights as half2 pairs

    const int bc   = blockIdx.x >> 3;            // (b*C + c), TILES == 8
    const int tile = blockIdx.x & (TILES - 1);
    const int c    = bc & (C_ - 1);

    const int t = threadIdx.x;
    if (t < NW_) {
        const float mur = mu_real[t];
        const float mui = mu_imag[t];
        // A = -log2(e)/(2*sigma); fold log2e so exp() is a single EX2
        const float A  = -0.72134752044448169f / stddev[t];
        const float Bc = -2.0f * A * mur;
        const float Cc = -2.0f * A * mui;
        const float Dc = A * (mur * mur + mui * mui);
        s_ab[t] = make_ulonglong2(pack2(A,  A),  pack2(Bc, Bc));
        s_cd[t] = make_ulonglong2(pack2(Cc, Cc), pack2(Dc, Dc));
        const float wr = w_real[c * NW_ + t];
        const float wi = w_imag[c * NW_ + t];
        s_w[t].wr2 = __floats2half2_rn(wr, wr);
        s_w[t].wi2 = __floats2half2_rn(wi, wi);
    }
    __syncthreads();

    const int p0   = tile * (TPB * PPT) + t * PPT;   // 2 consecutive pixels
    const int gidx = bc * HW_ + p0;                  // 8B-aligned

    const float2 xr = *reinterpret_cast<const float2*>(x_real + gidx);
    const float2 xi = *reinterpret_cast<const float2*>(x_imag + gidx);

    // s = |x|^2 per pixel (once), pack pixel-pair operands
    const float s0 = fmaf(xr.x, xr.x, xi.x * xi.x);
    const float s1 = fmaf(xr.y, xr.y, xi.y * xi.y);

    const u64 s01  = pack2(s0, s1);
    const u64 xr01 = pack2(xr.x, xr.y);
    const u64 xi01 = pack2(xi.x, xi.y);

    float ar0 = 0.f, ar1 = 0.f;      // fp32 master accumulators
    float ai0 = 0.f, ai1 = 0.f;

    // 8 chunks of 8 centers: half2 chunk accumulators (<=8 terms -> ~1e-4
    // noise) drained exactly into fp32 between chunks. Numerics == R10.
#pragma unroll
    for (int w8 = 0; w8 < NW_ / 8; ++w8) {
        __half2 accr = __floats2half2_rn(0.f, 0.f);
        __half2 acci = accr;

#pragma unroll
        for (int k = 0; k < 8; ++k) {
            const int w = w8 * 8 + k;
            const ulonglong2 ab = s_ab[w];   // LDS.128 broadcast
            const ulonglong2 cd = s_cd[w];   // LDS.128 broadcast

            // arg = A*s + B*xr + C*xi + D : 3 packed FMAs for the pixel pair
            const u64 g = fma2(ab.x, s01, fma2(ab.y, xr01, fma2(cd.x, xi01, cd.y)));

            // 1 CVT + 1 packed MUFU for both pixels
            const __half2 e = packed_exp2(g);

            const WPair wv = s_w[w];         // LDS.64 broadcast
            accr = __hfma2(e, wv.wr2, accr); // 2 HFMA2: real+imag, both pixels
            acci = __hfma2(e, wv.wi2, acci);
        }

        const float2 fr = __half22float2(accr);
        const float2 fi = __half22float2(acci);
        ar0 += fr.x;  ar1 += fr.y;
        ai0 += fi.x;  ai1 += fi.y;
    }

    const float br = b_real[c];
    const float bi = b_imag[c];

    // Output layout (B,C,H,W,2): 2 pixels -> one 16B store
    float4* op = reinterpret_cast<float4*>(out + 2 * gidx);
    op[0] = make_float4(ar0 + br, ai0 + bi, ar1 + br, ai1 + bi);
}

extern "C" void kernel_launch(void* const* d_in, const int* in_sizes, int n_in,
                              void* d_out, int out_size)
{
    const float* x_real  = (const float*)d_in[0];
    const float* x_imag  = (const float*)d_in[1];
    const float* w_real  = (const float*)d_in[2];
    const float* w_imag  = (const float*)d_in[3];
    const float* b_real  = (const float*)d_in[4];
    const float* b_imag  = (const float*)d_in[5];
    const float* mu_real = (const float*)d_in[6];
    const float* mu_imag = (const float*)d_in[7];
    const float* stddev  = (const float*)d_in[8];
    float* out = (float*)d_out;

    const int grid = B_ * C_ * TILES;   // 1024 blocks
    cplx_rbf_kernel<<<grid, TPB>>>(x_real, x_imag, w_real, w_imag,
                                   b_real, b_imag, mu_real, mu_imag,
                                   stddev, out);
}

// round 16
// speedup vs baseline: 1.4908x; 1.4908x over previous
#include <cuda_runtime.h>
#include <cuda_fp16.h>

// Problem constants (fixed by the reference: B=4, C=32, H=64, W=64, NW=64)
#define NW_   64
#define HW_   4096
#define C_    32
#define B_    4
#define TPB   256
#define PPT   1                       // 1 pixel/thread: 16K warps, occ ceiling 100%
#define TILES (HW_ / TPB)             // 16 blocks per (b,c) image
#define NPAIR (NW_ / 2)               // 32 center pairs

// Pack two fp32 args into f16x2 (one CVT) and take one packed MUFU exp2.
__device__ __forceinline__ __half2 pack_exp2(float a0, float a1) {
    unsigned u;
    asm("cvt.rn.f16x2.f32 %0, %1, %2;" : "=r"(u) : "f"(a1), "f"(a0));  // lo=a0
    __half2 h = *reinterpret_cast<__half2*>(&u);
    return h2exp2(h);
}

struct __align__(8) WPair { __half2 wr2, wi2; };  // {wr0,wr1},{wi0,wi1} -> 1 LDS.64

__global__ __launch_bounds__(TPB) void cplx_rbf_kernel(
    const float* __restrict__ x_real, const float* __restrict__ x_imag,
    const float* __restrict__ w_real, const float* __restrict__ w_imag,
    const float* __restrict__ b_real, const float* __restrict__ b_imag,
    const float* __restrict__ mu_real, const float* __restrict__ mu_imag,
    const float* __restrict__ stddev,
    float* __restrict__ out)
{
    // Center-PAIR interleaved coefficients: per iter 2x LDS.128 + 1x LDS.64,
    // two independent 3-FFMA chains (proven-fastest R10 instruction mix).
    __shared__ float4 s_p1[NPAIR];   // {A0, A1, B0, B1}
    __shared__ float4 s_p2[NPAIR];   // {C0, C1, D0, D1}
    __shared__ WPair  s_wp[NPAIR];   // {wr0,wr1}, {wi0,wi1}

    const int bc   = blockIdx.x >> 4;            // (b*C + c), TILES == 16
    const int tile = blockIdx.x & (TILES - 1);
    const int c    = bc & (C_ - 1);

    const int t = threadIdx.x;
    if (t < NPAIR) {
        const int w0 = 2 * t, w1 = 2 * t + 1;
        const float mur0 = mu_real[w0], mui0 = mu_imag[w0];
        const float mur1 = mu_real[w1], mui1 = mu_imag[w1];
        // A = -log2(e)/(2*sigma); fold log2e so exp() is a single EX2
        const float A0 = -0.72134752044448169f / stddev[w0];
        const float A1 = -0.72134752044448169f / stddev[w1];
        s_p1[t] = make_float4(A0, A1, -2.0f * A0 * mur0, -2.0f * A1 * mur1);
        s_p2[t] = make_float4(-2.0f * A0 * mui0, -2.0f * A1 * mui1,
                              A0 * (mur0 * mur0 + mui0 * mui0),
                              A1 * (mur1 * mur1 + mui1 * mui1));
        s_wp[t].wr2 = __floats2half2_rn(w_real[c * NW_ + w0], w_real[c * NW_ + w1]);
        s_wp[t].wi2 = __floats2half2_rn(w_imag[c * NW_ + w0], w_imag[c * NW_ + w1]);
    }
    __syncthreads();

    const int gidx = bc * HW_ + tile * TPB + t;   // one pixel per thread

    const float xr = x_real[gidx];
    const float xi = x_imag[gidx];
    const float s  = fmaf(xr, xr, xi * xi);       // |x|^2, reused for 64 centers

    float ar = 0.f, ai = 0.f;                     // fp32 master accumulators

    // 4 chunks of 8 center-pairs: half2 chunk accumulators hold per-lane
    // partial sums over <=8 terms (~1e-4 noise), drained exactly into fp32.
#pragma unroll
    for (int p8 = 0; p8 < NPAIR / 8; ++p8) {
        __half2 accr = __floats2half2_rn(0.f, 0.f);
        __half2 acci = accr;

#pragma unroll
        for (int k = 0; k < 8; ++k) {
            const int p = p8 * 8 + k;
            const float4 P1 = s_p1[p];   // LDS.128 broadcast
            const float4 P2 = s_p2[p];   // LDS.128 broadcast

            // Two independent fp32 arg chains (centers 2p, 2p+1)
            const float a0 = fmaf(P1.x, s, fmaf(P1.z, xr, fmaf(P2.x, xi, P2.z)));
            const float a1 = fmaf(P1.y, s, fmaf(P1.w, xr, fmaf(P2.y, xi, P2.w)));

            // 1 CVT + 1 packed MUFU for both centers
            const __half2 e = pack_exp2(a0, a1);

            const WPair wp = s_wp[p];        // LDS.64 broadcast
            accr = __hfma2(e, wp.wr2, accr); // lane-parallel center partial sums
            acci = __hfma2(e, wp.wi2, acci);
        }

        const float2 fr = __half22float2(accr);
        const float2 fi = __half22float2(acci);
        ar += fr.x;  ar += fr.y;             // horizontal drain, fp32
        ai += fi.x;  ai += fi.y;
    }

    // Output layout (B,C,H,W,2): one pixel -> 8B store {re, im}
    float2* op = reinterpret_cast<float2*>(out + 2 * gidx);
    op[0] = make_float2(ar + b_real[c], ai + b_imag[c]);
}

extern "C" void kernel_launch(void* const* d_in, const int* in_sizes, int n_in,
                              void* d_out, int out_size)
{
    const float* x_real  = (const float*)d_in[0];
    const float* x_imag  = (const float*)d_in[1];
    const float* w_real  = (const float*)d_in[2];
    const float* w_imag  = (const float*)d_in[3];
    const float* b_real  = (const float*)d_in[4];
    const float* b_imag  = (const float*)d_in[5];
    const float* mu_real = (const float*)d_in[6];
    const float* mu_imag = (const float*)d_in[7];
    const float* stddev  = (const float*)d_in[8];
    float* out = (float*)d_out;

    const int grid = B_ * C_ * TILES;   // 2048 blocks
    cplx_rbf_kernel<<<grid, TPB>>>(x_real, x_imag, w_real, w_imag,
                                   b_real, b_imag, mu_real, mu_imag,
                                   stddev, out);
}